// round 15
// baseline (speedup 1.0000x reference)
#include <cuda_runtime.h>
#include <cuda_bf16.h>
#include <stdint.h>

#define N_NODES 100000
#define N_EDGES 2000000
#define PER 12
#define H 128
#define TILE_M 128
#define NT (N_EDGES / TILE_M)   // 15625
#define GRID 296                // 2 CTAs per SM
#define NTHREADS 256            // 8 warps, all gather+MMA
#define NPRE 6250               // precompute blocks (50000 warps, 2 nodes/warp)
#define NPREP 64                // prep blocks (2 W2 columns each)

// P/Q fixed-point: step 2^-13 (max 4.0); A15 = Pint+Qint (max ~28K < 32639)
#define INV_PQ 8192.0f

// ---------------- device scratch (allocation-free rule) ----------------
__device__ short g_Pi[N_NODES * H];      // quantized node_embs @ W1[:12] + b1
__device__ short g_Qi[N_NODES * H];      // quantized node_embs @ W1[12:]
__device__ unsigned char g_B[32768];     // W2^T int8: hi plane 16KB, lo plane 16KB (swizzled)
__device__ float g_C1[H];                // per-col scale
__device__ double g_sum;

// ---------------- helpers ----------------
__device__ __forceinline__ uint32_t smem_to_u32(const void* p) {
    uint32_t a;
    asm("{ .reg .u64 t; cvta.to.shared.u64 t, %1; cvt.u32.u64 %0, t; }" : "=r"(a) : "l"(p));
    return a;
}
#define LDSM_X4(r0, r1, r2, r3, addr) \
    asm volatile("ldmatrix.sync.aligned.m8n8.x4.shared.b16 {%0,%1,%2,%3}, [%4];" \
        : "=r"(r0), "=r"(r1), "=r"(r2), "=r"(r3) : "r"(addr))
#define MMAS8(d, a0, a1, a2, a3, b0, b1) \
    asm volatile("mma.sync.aligned.m16n8k32.row.col.s32.s8.s8.s32 " \
        "{%0,%1,%2,%3}, {%4,%5,%6,%7}, {%8,%9}, {%0,%1,%2,%3};" \
        : "+r"((d)[0]), "+r"((d)[1]), "+r"((d)[2]), "+r"((d)[3]) \
        : "r"(a0), "r"(a1), "r"(a2), "r"(a3), "r"(b0), "r"(b1))
#define PACK_S16(d, vhi, vlo) \
    asm("cvt.pack.sat.s16.s32 %0, %1, %2;" : "=r"(d) : "r"(vhi), "r"(vlo))
#define FMA2(acc, a, b) \
    asm("fma.rn.f32x2 %0, %1, %2, %0;" : "+l"(acc) : "l"(a), "l"(b))
#define PACKF2(d, x) \
    asm("mov.b64 %0, {%1, %1};" : "=l"(d) : "f"(x))
#define UNPACKF2(lo, hi, v) \
    asm("mov.b64 {%0, %1}, %2;" : "=f"(lo), "=f"(hi) : "l"(v))

// quantize 4 packed-int16 h1 values: relu, split 15-bit -> int8 hi/lo planes.
__device__ __forceinline__ void quant4(uint2 p, uint2 q, uint32_t& hi, uint32_t& lo) {
    uint32_t s0 = __vaddss2(p.x, q.x);
    uint32_t s1 = __vaddss2(p.y, q.y);
    s0 = __vmaxs2(s0, 0u);
    s1 = __vmaxs2(s1, 0u);
    s0 += 0x00800080u;                       // +128 per lane (round for hi split)
    s1 += 0x00800080u;
    hi = __byte_perm(s0, s1, 0x7531);        // high bytes: (A+128)>>8 in [0,127]
    lo = __byte_perm(s0, s1, 0x6420) ^ 0x80808080u;  // low bytes re-biased to s8
}

// ---------------- SMEM layout (edge kernel) ----------------
#define SO_EP   0        // 128 x float4 {b2, Wv+Wa, Wa, C1}
#define SO_RED  2048
#define SO_B    4096     // B hi 16KB, lo 16KB
#define SMEM_TOTAL 36864

// ---------------------------------------------------------------------------
// Kernel A (merged): blocks [0,NPRE): P/Q int16 precompute, 2 nodes/warp,
// packed fma.rn.f32x2 accumulation (low regs -> high occupancy).
// Blocks [NPRE,NPRE+NPREP): W2^T quantize.
// ---------------------------------------------------------------------------
__global__ void precompute_prep_kernel(const float* __restrict__ E,
                                       const float* __restrict__ W1,
                                       const float* __restrict__ b1,
                                       const float* __restrict__ W2) {
    if (blockIdx.x >= NPRE) {
        // ---------------- prep part: 2 W2 columns per block ----------------
        __shared__ float red2[8];
        int b = blockIdx.x - NPRE;
        int half = threadIdx.x >> 7;           // 0/1
        int n = 2 * b + half;
        int k = threadIdx.x & 127;
        float w = W2[k * H + n];
        float m = fabsf(w);
#pragma unroll
        for (int o = 16; o; o >>= 1) m = fmaxf(m, __shfl_xor_sync(0xffffffffu, m, o));
        if ((threadIdx.x & 31) == 0) red2[threadIdx.x >> 5] = m;
        __syncthreads();
        float t = fmaxf(fmaxf(red2[4 * half + 0], red2[4 * half + 1]),
                        fmaxf(red2[4 * half + 2], red2[4 * half + 3]));
        t = fmaxf(t, 1e-20f);
        int B15 = __float2int_rn(w * (32512.0f / t));
        int hi = (B15 + 128) >> 8;
        int lo = B15 - (hi << 8);
        uint32_t addr = ((uint32_t)n << 7) + ((((uint32_t)(k >> 4)) ^ (uint32_t)(n & 7)) << 4)
                      + ((uint32_t)k & 15u);
        g_B[addr] = (unsigned char)(hi & 255);
        g_B[addr + 16384] = (unsigned char)(lo & 255);
        if (k == 0) g_C1[n] = t * (8.0f / 32512.0f);
        return;
    }
    // ---------------- precompute part: 2 nodes per warp ----------------
    if (blockIdx.x == 0 && threadIdx.x == 0) g_sum = 0.0;
    int warp = (blockIdx.x * blockDim.x + threadIdx.x) >> 5;
    int lane = threadIdx.x & 31;
    int node0 = 2 * warp;                  // N_NODES is even
    if (node0 >= N_NODES) return;
    // 2 nodes x 12 floats = 24 e-values held across lanes (1 reg/lane)
    const float* eb_ = E + node0 * PER;
    float ev = (lane < 24) ? __ldg(eb_ + lane) : 0.f;

    int j = lane << 2;
    ulonglong2 bj = *(const ulonglong2*)(b1 + j);
    uint64_t pa0 = bj.x, pa1 = bj.y, pb0 = bj.x, pb1 = bj.y;
    uint64_t qa0 = 0ull, qa1 = 0ull, qb0 = 0ull, qb1 = 0ull;
#pragma unroll
    for (int k = 0; k < PER; ++k) {
        ulonglong2 wa = *(const ulonglong2*)(W1 + k * H + j);
        ulonglong2 wb = *(const ulonglong2*)(W1 + (k + PER) * H + j);
        float ea = __shfl_sync(0xffffffffu, ev, k);          // node0: floats 0..11
        float ebv = __shfl_sync(0xffffffffu, ev, 12 + k);    // node1: floats 12..23
        uint64_t e2;
        PACKF2(e2, ea);
        FMA2(pa0, e2, wa.x); FMA2(pa1, e2, wa.y);
        FMA2(qa0, e2, wb.x); FMA2(qa1, e2, wb.y);
        PACKF2(e2, ebv);
        FMA2(pb0, e2, wa.x); FMA2(pb1, e2, wa.y);
        FMA2(qb0, e2, wb.x); FMA2(qb1, e2, wb.y);
    }
#define STORE_PQ2(a0v, a1v, arr, node) do { \
        float x, y, z, wv; \
        UNPACKF2(x, y, a0v); UNPACKF2(z, wv, a1v); \
        int v0 = __float2int_rn(x * INV_PQ), v1 = __float2int_rn(y * INV_PQ); \
        int v2 = __float2int_rn(z * INV_PQ), v3 = __float2int_rn(wv * INV_PQ); \
        uint2 wval; PACK_S16(wval.x, v1, v0); PACK_S16(wval.y, v3, v2); \
        *(uint2*)((arr) + (node) * H + j) = wval; \
    } while (0)
    STORE_PQ2(pa0, pa1, g_Pi, node0);
    STORE_PQ2(qa0, qa1, g_Qi, node0);
    STORE_PQ2(pb0, pb1, g_Pi, node0 + 1);
    STORE_PQ2(qb0, qb1, g_Qi, node0 + 1);
#undef STORE_PQ2
}

// ---------------------------------------------------------------------------
// Edge kernel (exact R9/R12/R13): register-direct gather + SIMD quantize,
// 192 s8 MMAs/warp/tile, combined accumulator, warp-local epilogue.
// ---------------------------------------------------------------------------
extern __shared__ unsigned char smx[];

__global__ void __launch_bounds__(NTHREADS, 2)
edge_kernel(const int* __restrict__ src, const int* __restrict__ dst,
            const float* __restrict__ b2, const float* __restrict__ Wv,
            const float* __restrict__ bv, const float* __restrict__ Wa,
            float* __restrict__ out) {
    uint32_t sb = smem_to_u32(smx);
    int tid = threadIdx.x, wid = tid >> 5, lane = tid & 31;

    if (tid < H) {
        float wa = Wa[tid];
        ((float4*)(smx + SO_EP))[tid] = make_float4(b2[tid], Wv[tid] + wa, wa, g_C1[tid]);
    }
    {   // stage pre-swizzled int8 W2^T (hi+lo planes) into SMEM
        const int4* s1 = (const int4*)g_B;
        int4* d1 = (int4*)(smx + SO_B);
        for (int i = tid; i < 2048; i += NTHREADS) d1[i] = s1[i];
    }
    __syncthreads();
    float bv0 = __ldg(bv);
    float asum = 0.f;

    int w = wid;
    int row0 = 16 * w + (lane >> 2);           // this lane's first M row
    int kq = lane & 3;                         // uint2 index: shorts 4(lane&3)..+3
    uint32_t m = (uint32_t)(lane >> 3);
    uint32_t lr7 = (uint32_t)(lane & 7);
    uint32_t b_lane_n = ((m >> 1u) << 3) + lr7;
    uint32_t b_cb = m & 1u;
    uint32_t Bhi = sb + SO_B;
    const float4* ep = (const float4*)(smx + SO_EP);

    for (int t = blockIdx.x; t < NT; t += GRID) {
        int s0 = __ldg(src + t * TILE_M + row0);
        int d0 = __ldg(dst + t * TILE_M + row0);
        int s1 = __ldg(src + t * TILE_M + row0 + 8);
        int d1 = __ldg(dst + t * TILE_M + row0 + 8);
        const uint2* P0 = (const uint2*)(g_Pi + s0 * H) + kq;
        const uint2* Q0 = (const uint2*)(g_Qi + d0 * H) + kq;
        const uint2* P1 = (const uint2*)(g_Pi + s1 * H) + kq;
        const uint2* Q1 = (const uint2*)(g_Qi + d1 * H) + kq;

        uint32_t Ah[4][4], Al[4][4];   // [ks][a0..a3]
#pragma unroll
        for (int ks = 0; ks < 4; ++ks) {
            quant4(P0[ks * 8],     Q0[ks * 8],     Ah[ks][0], Al[ks][0]);
            quant4(P1[ks * 8],     Q1[ks * 8],     Ah[ks][1], Al[ks][1]);
            quant4(P0[ks * 8 + 4], Q0[ks * 8 + 4], Ah[ks][2], Al[ks][2]);
            quant4(P1[ks * 8 + 4], Q1[ks * 8 + 4], Ah[ks][3], Al[ks][3]);
        }

        float qp0 = 0.f, av0 = 0.f, qp1 = 0.f, av1 = 0.f;
#pragma unroll
        for (int hn = 0; hn < 2; ++hn) {
            int acc[8][4];
#pragma unroll
            for (int i = 0; i < 8; ++i)
#pragma unroll
                for (int r = 0; r < 4; ++r) acc[i][r] = 0;

            // ---- pass 1: Ahi x Bhi ----
#pragma unroll
            for (int ks = 0; ks < 4; ++ks) {
                uint32_t kssw = (((uint32_t)(2 * ks) + b_cb) ^ lr7) << 4;
#pragma unroll
                for (int j = 0; j < 4; ++j) {
                    uint32_t baddr = Bhi + (((uint32_t)(64 * hn + 16 * j) + b_lane_n) << 7) + kssw;
                    uint32_t h0, h1, h2, h3;
                    LDSM_X4(h0, h1, h2, h3, baddr);
                    MMAS8(acc[2 * j],     Ah[ks][0], Ah[ks][1], Ah[ks][2], Ah[ks][3], h0, h1);
                    MMAS8(acc[2 * j + 1], Ah[ks][0], Ah[ks][1], Ah[ks][2], Ah[ks][3], h2, h3);
                }
            }
#pragma unroll
            for (int i = 0; i < 8; ++i)
#pragma unroll
                for (int r = 0; r < 4; ++r) acc[i][r] <<= 8;

            // ---- pass 2: Ahi x Blo + Alo x Bhi ----
#pragma unroll
            for (int ks = 0; ks < 4; ++ks) {
                uint32_t kssw = (((uint32_t)(2 * ks) + b_cb) ^ lr7) << 4;
#pragma unroll
                for (int j = 0; j < 4; ++j) {
                    uint32_t baddr = Bhi + (((uint32_t)(64 * hn + 16 * j) + b_lane_n) << 7) + kssw;
                    uint32_t h0, h1, h2, h3, l0, l1, l2, l3;
                    LDSM_X4(h0, h1, h2, h3, baddr);
                    LDSM_X4(l0, l1, l2, l3, baddr + 16384u);
                    MMAS8(acc[2 * j],     Ah[ks][0], Ah[ks][1], Ah[ks][2], Ah[ks][3], l0, l1);
                    MMAS8(acc[2 * j + 1], Ah[ks][0], Ah[ks][1], Ah[ks][2], Ah[ks][3], l2, l3);
                    MMAS8(acc[2 * j],     Al[ks][0], Al[ks][1], Al[ks][2], Al[ks][3], h0, h1);
                    MMAS8(acc[2 * j + 1], Al[ks][0], Al[ks][1], Al[ks][2], Al[ks][3], h2, h3);
                }
            }

            // ---- epilogue for this n-half (warp-local) ----
#pragma unroll
            for (int nb = 0; nb < 8; ++nb) {
                int c = 64 * hn + 8 * nb + 2 * (lane & 3);
                float4 e0 = ep[c], e1 = ep[c + 1];
                float C20 = e0.w * 0.00390625f;
                float C21 = e1.w * 0.00390625f;
                float h;
                h = fmaxf(fmaf(C20, (float)acc[nb][0], e0.x), 0.f); qp0 += h * e0.y; av0 += h * e0.z;
                h = fmaxf(fmaf(C21, (float)acc[nb][1], e1.x), 0.f); qp0 += h * e1.y; av0 += h * e1.z;
                h = fmaxf(fmaf(C20, (float)acc[nb][2], e0.x), 0.f); qp1 += h * e0.y; av1 += h * e0.z;
                h = fmaxf(fmaf(C21, (float)acc[nb][3], e1.x), 0.f); qp1 += h * e1.y; av1 += h * e1.z;
            }
        }

        qp0 += __shfl_xor_sync(0xffffffffu, qp0, 1); qp0 += __shfl_xor_sync(0xffffffffu, qp0, 2);
        av0 += __shfl_xor_sync(0xffffffffu, av0, 1); av0 += __shfl_xor_sync(0xffffffffu, av0, 2);
        qp1 += __shfl_xor_sync(0xffffffffu, qp1, 1); qp1 += __shfl_xor_sync(0xffffffffu, qp1, 2);
        av1 += __shfl_xor_sync(0xffffffffu, av1, 1); av1 += __shfl_xor_sync(0xffffffffu, av1, 2);
        if ((lane & 3) == 0) {
            out[t * TILE_M + row0] = qp0 + bv0;
            out[t * TILE_M + row0 + 8] = qp1 + bv0;
            asum += av0 + av1;
        }
    }

    __syncthreads();
#pragma unroll
    for (int o = 16; o; o >>= 1) asum += __shfl_xor_sync(0xffffffffu, asum, o);
    float* red = (float*)(smx + SO_RED);
    if (lane == 0) red[wid] = asum;
    __syncthreads();
    if (tid == 0) {
        float sf = 0.f;
#pragma unroll
        for (int i = 0; i < 8; ++i) sf += red[i];
        atomicAdd(&g_sum, (double)sf);
    }
}

// ---------------------------------------------------------------------------
// Finalize: float4 grid-stride mean subtraction
// ---------------------------------------------------------------------------
__global__ void finalize_kernel(float* __restrict__ out) {
    float mean = (float)(g_sum * (1.0 / (double)N_EDGES));
    int stride = gridDim.x * blockDim.x;
    for (int i = blockIdx.x * blockDim.x + threadIdx.x; i < N_EDGES / 4; i += stride) {
        float4 v = ((const float4*)out)[i];
        v.x -= mean; v.y -= mean; v.z -= mean; v.w -= mean;
        ((float4*)out)[i] = v;
    }
}

// ---------------------------------------------------------------------------
extern "C" void kernel_launch(void* const* d_in, const int* in_sizes, int n_in,
                              void* d_out, int out_size) {
    const float* node_embs = (const float*)d_in[0];
    const int*   src       = (const int*)d_in[1];
    const int*   dst       = (const int*)d_in[2];
    const float* W1        = (const float*)d_in[3];
    const float* b1        = (const float*)d_in[4];
    const float* W2        = (const float*)d_in[5];
    const float* b2        = (const float*)d_in[6];
    const float* Wv        = (const float*)d_in[7];
    const float* bv        = (const float*)d_in[8];
    const float* Wa        = (const float*)d_in[9];
    // ba (d_in[10]) cancels algebraically
    float* out = (float*)d_out;

    precompute_prep_kernel<<<NPRE + NPREP, 256>>>(node_embs, W1, b1, W2);

    cudaFuncSetAttribute(edge_kernel,
                         cudaFuncAttributeMaxDynamicSharedMemorySize, SMEM_TOTAL);
    edge_kernel<<<GRID, NTHREADS, SMEM_TOTAL>>>(src, dst, b2, Wv, bv, Wa, out);

    finalize_kernel<<<GRID, NTHREADS>>>(out);
}

// round 16
// speedup vs baseline: 1.0149x; 1.0149x over previous
#include <cuda_runtime.h>
#include <cuda_bf16.h>
#include <stdint.h>

#define N_NODES 100000
#define N_EDGES 2000000
#define PER 12
#define H 128
#define TILE_M 128
#define NT (N_EDGES / TILE_M)   // 15625
#define GRID 296                // 2 CTAs per SM
#define NTHREADS 256            // 8 warps, all gather+MMA
#define NPRE 3125               // precompute blocks (25000 warps, 4 nodes/warp)
#define NPREP 64                // prep blocks (2 W2 columns each)

// P/Q fixed-point: step 2^-13 (max 4.0); A15 = Pint+Qint (max ~28K < 32639)
#define INV_PQ 8192.0f

// ---------------- device scratch (allocation-free rule) ----------------
__device__ short g_Pi[N_NODES * H];      // quantized node_embs @ W1[:12] + b1
__device__ short g_Qi[N_NODES * H];      // quantized node_embs @ W1[12:]
__device__ unsigned char g_B[32768];     // W2^T int8: hi plane 16KB, lo plane 16KB (swizzled)
__device__ float g_C1[H];                // per-col scale
__device__ double g_sum;

// ---------------- helpers ----------------
__device__ __forceinline__ uint32_t smem_to_u32(const void* p) {
    uint32_t a;
    asm("{ .reg .u64 t; cvta.to.shared.u64 t, %1; cvt.u32.u64 %0, t; }" : "=r"(a) : "l"(p));
    return a;
}
#define LDSM_X4(r0, r1, r2, r3, addr) \
    asm volatile("ldmatrix.sync.aligned.m8n8.x4.shared.b16 {%0,%1,%2,%3}, [%4];" \
        : "=r"(r0), "=r"(r1), "=r"(r2), "=r"(r3) : "r"(addr))
#define MMAS8(d, a0, a1, a2, a3, b0, b1) \
    asm volatile("mma.sync.aligned.m16n8k32.row.col.s32.s8.s8.s32 " \
        "{%0,%1,%2,%3}, {%4,%5,%6,%7}, {%8,%9}, {%0,%1,%2,%3};" \
        : "+r"((d)[0]), "+r"((d)[1]), "+r"((d)[2]), "+r"((d)[3]) \
        : "r"(a0), "r"(a1), "r"(a2), "r"(a3), "r"(b0), "r"(b1))
#define PACK_S16(d, vhi, vlo) \
    asm("cvt.pack.sat.s16.s32 %0, %1, %2;" : "=r"(d) : "r"(vhi), "r"(vlo))
#define FMA2(acc, a, b) \
    asm("fma.rn.f32x2 %0, %1, %2, %0;" : "+l"(acc) : "l"(a), "l"(b))
#define PACKF2(d, x) \
    asm("mov.b64 %0, {%1, %1};" : "=l"(d) : "f"(x))
#define UNPACKF2(lo, hi, v) \
    asm("mov.b64 {%0, %1}, %2;" : "=f"(lo), "=f"(hi) : "l"(v))

// quantize 4 packed-int16 h1 values: relu, split 15-bit -> int8 hi/lo planes.
__device__ __forceinline__ void quant4(uint2 p, uint2 q, uint32_t& hi, uint32_t& lo) {
    uint32_t s0 = __vaddss2(p.x, q.x);
    uint32_t s1 = __vaddss2(p.y, q.y);
    s0 = __vmaxs2(s0, 0u);
    s1 = __vmaxs2(s1, 0u);
    s0 += 0x00800080u;                       // +128 per lane (round for hi split)
    s1 += 0x00800080u;
    hi = __byte_perm(s0, s1, 0x7531);        // high bytes: (A+128)>>8 in [0,127]
    lo = __byte_perm(s0, s1, 0x6420) ^ 0x80808080u;  // low bytes re-biased to s8
}

// ---------------- SMEM layout (edge kernel) ----------------
#define SO_EP   0        // 128 x float4 {b2, Wv+Wa, Wa, C1}
#define SO_RED  2048
#define SO_B    4096     // B hi 16KB, lo 16KB
#define SMEM_TOTAL 36864

// ---------------------------------------------------------------------------
// Kernel A (merged): blocks [0,NPRE): P/Q int16 precompute, 4 nodes/warp,
// FMA2 accumulation, W1 staged in SMEM once per block (8x L1-traffic cut).
// Blocks [NPRE,NPRE+NPREP): W2^T quantize.
// ---------------------------------------------------------------------------
__global__ void precompute_prep_kernel(const float* __restrict__ E,
                                       const float* __restrict__ W1,
                                       const float* __restrict__ b1,
                                       const float* __restrict__ W2) {
    __shared__ float w1s[2 * PER * H];   // 12 KB: rows 0..11 = W1_top, 12..23 = W1_bot
    if (blockIdx.x >= NPRE) {
        // ---------------- prep part: 2 W2 columns per block ----------------
        __shared__ float red2[8];
        int b = blockIdx.x - NPRE;
        int half = threadIdx.x >> 7;           // 0/1
        int n = 2 * b + half;
        int k = threadIdx.x & 127;
        float w = W2[k * H + n];
        float m = fabsf(w);
#pragma unroll
        for (int o = 16; o; o >>= 1) m = fmaxf(m, __shfl_xor_sync(0xffffffffu, m, o));
        if ((threadIdx.x & 31) == 0) red2[threadIdx.x >> 5] = m;
        __syncthreads();
        float t = fmaxf(fmaxf(red2[4 * half + 0], red2[4 * half + 1]),
                        fmaxf(red2[4 * half + 2], red2[4 * half + 3]));
        t = fmaxf(t, 1e-20f);
        int B15 = __float2int_rn(w * (32512.0f / t));
        int hi = (B15 + 128) >> 8;
        int lo = B15 - (hi << 8);
        uint32_t addr = ((uint32_t)n << 7) + ((((uint32_t)(k >> 4)) ^ (uint32_t)(n & 7)) << 4)
                      + ((uint32_t)k & 15u);
        g_B[addr] = (unsigned char)(hi & 255);
        g_B[addr + 16384] = (unsigned char)(lo & 255);
        if (k == 0) g_C1[n] = t * (8.0f / 32512.0f);
        return;
    }
    // ---------------- precompute part: 4 nodes per warp ----------------
    if (blockIdx.x == 0 && threadIdx.x == 0) g_sum = 0.0;
    // stage W1 into SMEM (768 float4s over 256 threads)
    for (int i = threadIdx.x; i < 2 * PER * H / 4; i += NTHREADS)
        ((float4*)w1s)[i] = ((const float4*)W1)[i];
    __syncthreads();

    int warp = (blockIdx.x * blockDim.x + threadIdx.x) >> 5;
    int lane = threadIdx.x & 31;
    int node0 = 4 * warp;                  // N_NODES % 4 == 0
    if (node0 >= N_NODES) return;
    // 4 nodes x 12 floats = 48 e-values held across lanes (2 regs/lane)
    const float* eb_ = E + node0 * PER;
    float ev0 = __ldg(eb_ + lane);
    float ev1 = (lane < 16) ? __ldg(eb_ + 32 + lane) : 0.f;

    int j = lane << 2;
    ulonglong2 bj = *(const ulonglong2*)(b1 + j);
    uint64_t pa[4][2], qa[4][2];
#pragma unroll
    for (int i = 0; i < 4; ++i) {
        pa[i][0] = bj.x; pa[i][1] = bj.y;
        qa[i][0] = 0ull; qa[i][1] = 0ull;
    }
#pragma unroll
    for (int k = 0; k < PER; ++k) {
        ulonglong2 wa = *(const ulonglong2*)(w1s + k * H + j);
        ulonglong2 wb = *(const ulonglong2*)(w1s + (k + PER) * H + j);
        float ea = __shfl_sync(0xffffffffu, ev0, k);            // node0: floats 0..11
        float ebv = __shfl_sync(0xffffffffu, ev0, 12 + k);      // node1: floats 12..23
        float ec = (k < 8) ? __shfl_sync(0xffffffffu, ev0, 24 + k)
                           : __shfl_sync(0xffffffffu, ev1, k - 8);   // node2: 24..35
        float ed = __shfl_sync(0xffffffffu, ev1, 4 + k);        // node3: floats 36..47
        uint64_t e2;
        PACKF2(e2, ea);
        FMA2(pa[0][0], e2, wa.x); FMA2(pa[0][1], e2, wa.y);
        FMA2(qa[0][0], e2, wb.x); FMA2(qa[0][1], e2, wb.y);
        PACKF2(e2, ebv);
        FMA2(pa[1][0], e2, wa.x); FMA2(pa[1][1], e2, wa.y);
        FMA2(qa[1][0], e2, wb.x); FMA2(qa[1][1], e2, wb.y);
        PACKF2(e2, ec);
        FMA2(pa[2][0], e2, wa.x); FMA2(pa[2][1], e2, wa.y);
        FMA2(qa[2][0], e2, wb.x); FMA2(qa[2][1], e2, wb.y);
        PACKF2(e2, ed);
        FMA2(pa[3][0], e2, wa.x); FMA2(pa[3][1], e2, wa.y);
        FMA2(qa[3][0], e2, wb.x); FMA2(qa[3][1], e2, wb.y);
    }
#pragma unroll
    for (int i = 0; i < 4; ++i) {
        float x, y, z, wv;
        UNPACKF2(x, y, pa[i][0]); UNPACKF2(z, wv, pa[i][1]);
        int v0 = __float2int_rn(x * INV_PQ), v1 = __float2int_rn(y * INV_PQ);
        int v2 = __float2int_rn(z * INV_PQ), v3 = __float2int_rn(wv * INV_PQ);
        uint2 wval;
        PACK_S16(wval.x, v1, v0); PACK_S16(wval.y, v3, v2);
        *(uint2*)(g_Pi + (node0 + i) * H + j) = wval;
        UNPACKF2(x, y, qa[i][0]); UNPACKF2(z, wv, qa[i][1]);
        v0 = __float2int_rn(x * INV_PQ); v1 = __float2int_rn(y * INV_PQ);
        v2 = __float2int_rn(z * INV_PQ); v3 = __float2int_rn(wv * INV_PQ);
        PACK_S16(wval.x, v1, v0); PACK_S16(wval.y, v3, v2);
        *(uint2*)(g_Qi + (node0 + i) * H + j) = wval;
    }
}

// ---------------------------------------------------------------------------
// Edge kernel (exact R9/R12/R13/R14): register-direct gather + SIMD quantize,
// 192 s8 MMAs/warp/tile, combined accumulator, warp-local epilogue.
// ---------------------------------------------------------------------------
extern __shared__ unsigned char smx[];

__global__ void __launch_bounds__(NTHREADS, 2)
edge_kernel(const int* __restrict__ src, const int* __restrict__ dst,
            const float* __restrict__ b2, const float* __restrict__ Wv,
            const float* __restrict__ bv, const float* __restrict__ Wa,
            float* __restrict__ out) {
    uint32_t sb = smem_to_u32(smx);
    int tid = threadIdx.x, wid = tid >> 5, lane = tid & 31;

    if (tid < H) {
        float wa = Wa[tid];
        ((float4*)(smx + SO_EP))[tid] = make_float4(b2[tid], Wv[tid] + wa, wa, g_C1[tid]);
    }
    {   // stage pre-swizzled int8 W2^T (hi+lo planes) into SMEM
        const int4* s1 = (const int4*)g_B;
        int4* d1 = (int4*)(smx + SO_B);
        for (int i = tid; i < 2048; i += NTHREADS) d1[i] = s1[i];
    }
    __syncthreads();
    float bv0 = __ldg(bv);
    float asum = 0.f;

    int w = wid;
    int row0 = 16 * w + (lane >> 2);           // this lane's first M row
    int kq = lane & 3;                         // uint2 index: shorts 4(lane&3)..+3
    uint32_t m = (uint32_t)(lane >> 3);
    uint32_t lr7 = (uint32_t)(lane & 7);
    uint32_t b_lane_n = ((m >> 1u) << 3) + lr7;
    uint32_t b_cb = m & 1u;
    uint32_t Bhi = sb + SO_B;
    const float4* ep = (const float4*)(smx + SO_EP);

    for (int t = blockIdx.x; t < NT; t += GRID) {
        int s0 = __ldg(src + t * TILE_M + row0);
        int d0 = __ldg(dst + t * TILE_M + row0);
        int s1 = __ldg(src + t * TILE_M + row0 + 8);
        int d1 = __ldg(dst + t * TILE_M + row0 + 8);
        const uint2* P0 = (const uint2*)(g_Pi + s0 * H) + kq;
        const uint2* Q0 = (const uint2*)(g_Qi + d0 * H) + kq;
        const uint2* P1 = (const uint2*)(g_Pi + s1 * H) + kq;
        const uint2* Q1 = (const uint2*)(g_Qi + d1 * H) + kq;

        uint32_t Ah[4][4], Al[4][4];   // [ks][a0..a3]
#pragma unroll
        for (int ks = 0; ks < 4; ++ks) {
            quant4(P0[ks * 8],     Q0[ks * 8],     Ah[ks][0], Al[ks][0]);
            quant4(P1[ks * 8],     Q1[ks * 8],     Ah[ks][1], Al[ks][1]);
            quant4(P0[ks * 8 + 4], Q0[ks * 8 + 4], Ah[ks][2], Al[ks][2]);
            quant4(P1[ks * 8 + 4], Q1[ks * 8 + 4], Ah[ks][3], Al[ks][3]);
        }

        float qp0 = 0.f, av0 = 0.f, qp1 = 0.f, av1 = 0.f;
#pragma unroll
        for (int hn = 0; hn < 2; ++hn) {
            int acc[8][4];
#pragma unroll
            for (int i = 0; i < 8; ++i)
#pragma unroll
                for (int r = 0; r < 4; ++r) acc[i][r] = 0;

            // ---- pass 1: Ahi x Bhi ----
#pragma unroll
            for (int ks = 0; ks < 4; ++ks) {
                uint32_t kssw = (((uint32_t)(2 * ks) + b_cb) ^ lr7) << 4;
#pragma unroll
                for (int j = 0; j < 4; ++j) {
                    uint32_t baddr = Bhi + (((uint32_t)(64 * hn + 16 * j) + b_lane_n) << 7) + kssw;
                    uint32_t h0, h1, h2, h3;
                    LDSM_X4(h0, h1, h2, h3, baddr);
                    MMAS8(acc[2 * j],     Ah[ks][0], Ah[ks][1], Ah[ks][2], Ah[ks][3], h0, h1);
                    MMAS8(acc[2 * j + 1], Ah[ks][0], Ah[ks][1], Ah[ks][2], Ah[ks][3], h2, h3);
                }
            }
#pragma unroll
            for (int i = 0; i < 8; ++i)
#pragma unroll
                for (int r = 0; r < 4; ++r) acc[i][r] <<= 8;

            // ---- pass 2: Ahi x Blo + Alo x Bhi ----
#pragma unroll
            for (int ks = 0; ks < 4; ++ks) {
                uint32_t kssw = (((uint32_t)(2 * ks) + b_cb) ^ lr7) << 4;
#pragma unroll
                for (int j = 0; j < 4; ++j) {
                    uint32_t baddr = Bhi + (((uint32_t)(64 * hn + 16 * j) + b_lane_n) << 7) + kssw;
                    uint32_t h0, h1, h2, h3, l0, l1, l2, l3;
                    LDSM_X4(h0, h1, h2, h3, baddr);
                    LDSM_X4(l0, l1, l2, l3, baddr + 16384u);
                    MMAS8(acc[2 * j],     Ah[ks][0], Ah[ks][1], Ah[ks][2], Ah[ks][3], l0, l1);
                    MMAS8(acc[2 * j + 1], Ah[ks][0], Ah[ks][1], Ah[ks][2], Ah[ks][3], l2, l3);
                    MMAS8(acc[2 * j],     Al[ks][0], Al[ks][1], Al[ks][2], Al[ks][3], h0, h1);
                    MMAS8(acc[2 * j + 1], Al[ks][0], Al[ks][1], Al[ks][2], Al[ks][3], h2, h3);
                }
            }

            // ---- epilogue for this n-half (warp-local) ----
#pragma unroll
            for (int nb = 0; nb < 8; ++nb) {
                int c = 64 * hn + 8 * nb + 2 * (lane & 3);
                float4 e0 = ep[c], e1 = ep[c + 1];
                float C20 = e0.w * 0.00390625f;
                float C21 = e1.w * 0.00390625f;
                float h;
                h = fmaxf(fmaf(C20, (float)acc[nb][0], e0.x), 0.f); qp0 += h * e0.y; av0 += h * e0.z;
                h = fmaxf(fmaf(C21, (float)acc[nb][1], e1.x), 0.f); qp0 += h * e1.y; av0 += h * e1.z;
                h = fmaxf(fmaf(C20, (float)acc[nb][2], e0.x), 0.f); qp1 += h * e0.y; av1 += h * e0.z;
                h = fmaxf(fmaf(C21, (float)acc[nb][3], e1.x), 0.f); qp1 += h * e1.y; av1 += h * e1.z;
            }
        }

        qp0 += __shfl_xor_sync(0xffffffffu, qp0, 1); qp0 += __shfl_xor_sync(0xffffffffu, qp0, 2);
        av0 += __shfl_xor_sync(0xffffffffu, av0, 1); av0 += __shfl_xor_sync(0xffffffffu, av0, 2);
        qp1 += __shfl_xor_sync(0xffffffffu, qp1, 1); qp1 += __shfl_xor_sync(0xffffffffu, qp1, 2);
        av1 += __shfl_xor_sync(0xffffffffu, av1, 1); av1 += __shfl_xor_sync(0xffffffffu, av1, 2);
        if ((lane & 3) == 0) {
            out[t * TILE_M + row0] = qp0 + bv0;
            out[t * TILE_M + row0 + 8] = qp1 + bv0;
            asum += av0 + av1;
        }
    }

    __syncthreads();
#pragma unroll
    for (int o = 16; o; o >>= 1) asum += __shfl_xor_sync(0xffffffffu, asum, o);
    float* red = (float*)(smx + SO_RED);
    if (lane == 0) red[wid] = asum;
    __syncthreads();
    if (tid == 0) {
        float sf = 0.f;
#pragma unroll
        for (int i = 0; i < 8; ++i) sf += red[i];
        atomicAdd(&g_sum, (double)sf);
    }
}

// ---------------------------------------------------------------------------
// Finalize: float4 grid-stride mean subtraction
// ---------------------------------------------------------------------------
__global__ void finalize_kernel(float* __restrict__ out) {
    float mean = (float)(g_sum * (1.0 / (double)N_EDGES));
    int stride = gridDim.x * blockDim.x;
    for (int i = blockIdx.x * blockDim.x + threadIdx.x; i < N_EDGES / 4; i += stride) {
        float4 v = ((const float4*)out)[i];
        v.x -= mean; v.y -= mean; v.z -= mean; v.w -= mean;
        ((float4*)out)[i] = v;
    }
}

// ---------------------------------------------------------------------------
extern "C" void kernel_launch(void* const* d_in, const int* in_sizes, int n_in,
                              void* d_out, int out_size) {
    const float* node_embs = (const float*)d_in[0];
    const int*   src       = (const int*)d_in[1];
    const int*   dst       = (const int*)d_in[2];
    const float* W1        = (const float*)d_in[3];
    const float* b1        = (const float*)d_in[4];
    const float* W2        = (const float*)d_in[5];
    const float* b2        = (const float*)d_in[6];
    const float* Wv        = (const float*)d_in[7];
    const float* bv        = (const float*)d_in[8];
    const float* Wa        = (const float*)d_in[9];
    // ba (d_in[10]) cancels algebraically
    float* out = (float*)d_out;

    precompute_prep_kernel<<<NPRE + NPREP, 256>>>(node_embs, W1, b1, W2);

    cudaFuncSetAttribute(edge_kernel,
                         cudaFuncAttributeMaxDynamicSharedMemorySize, SMEM_TOTAL);
    edge_kernel<<<GRID, NTHREADS, SMEM_TOTAL>>>(src, dst, b2, Wv, bv, Wa, out);

    finalize_kernel<<<GRID, NTHREADS>>>(out);
}